// round 13
// baseline (speedup 1.0000x reference)
#include <cuda_runtime.h>
#include <math.h>

// B=16, L=2048, D=512, E=8, H=8, HD=64, F=2048
typedef unsigned long long ull;

__device__ float g_gates[128];
__device__ float g_hent[128];
__device__ float g_xn[16 * 512];
__device__ __align__(16) float g_qp[4 * 16 * 8 * 512];
__device__ __align__(16) float g_KQ[16 * 64 * 512];
__device__ __align__(16) float g_sc0[16 * 64 * 2048];
__device__ __align__(16) float g_sc1[16 * 64 * 2048];
__device__ __align__(16) float g_scores[16 * 64 * 2048];
__device__ __align__(16) float g_rp[4 * 16 * 64 * 512];
__device__ __align__(16) float g_ap[8 * 16 * 8 * 512];
__device__ __align__(16) float g_op[8 * 16 * 8 * 512];
__device__ __align__(16) float g_x[16 * 8 * 512];
__device__ __align__(16) float g_xo[16 * 8 * 512];
__device__ __align__(16) float g_h1p[4 * 16 * 8 * 2048];
__device__ __align__(16) float g_yp[8 * 16 * 8 * 512];

__device__ __forceinline__ ull pack2(float x) {
    ull r; unsigned u = __float_as_uint(x);
    asm("mov.b64 %0, {%1, %1};" : "=l"(r) : "r"(u));
    return r;
}
__device__ __forceinline__ void ffma2(ull& d, ull a, ull b) {
    asm("fma.rn.f32x2 %0, %1, %2, %0;" : "+l"(d) : "l"(a), "l"(b));
}
__device__ __forceinline__ float lo32(ull v) { return __uint_as_float((unsigned)v); }
__device__ __forceinline__ float hi32(ull v) { return __uint_as_float((unsigned)(v >> 32)); }

// ---- K1: gates ----
__global__ void k_gates(const float* __restrict__ q, const float* __restrict__ wg) {
    int b = blockIdx.x, t = threadIdx.x;
    __shared__ float part[256];
    int e = t & 7, chunk = t >> 3;
    float s = 0.f;
    for (int i = 0; i < 16; i++) {
        int d = chunk * 16 + i;
        s += q[b * 512 + d] * wg[d * 8 + e];
    }
    part[t] = s;
    __syncthreads();
    for (int st = 128; st >= 8; st >>= 1) {
        if (t < st) part[t] += part[t + st];
        __syncthreads();
    }
    if (t == 0) {
        float m = part[0];
        for (int i = 1; i < 8; i++) m = fmaxf(m, part[i]);
        float z = 0.f, ex[8];
        for (int i = 0; i < 8; i++) { ex[i] = __expf(part[i] - m); z += ex[i]; }
        float rz = 1.f / z;
        for (int i = 0; i < 8; i++) g_gates[b * 8 + i] = ex[i] * rz;
    }
}

// ---- K2: LN(query) -> xn ----
__global__ void k_lnq(const float* __restrict__ q) {
    int b = blockIdx.x, t = threadIdx.x;
    __shared__ float r1[256], r2[256];
    float x0 = q[b * 512 + t], x1 = q[b * 512 + t + 256];
    r1[t] = x0 + x1; r2[t] = x0 * x0 + x1 * x1;
    __syncthreads();
    for (int s = 128; s > 0; s >>= 1) {
        if (t < s) { r1[t] += r1[t + s]; r2[t] += r2[t + s]; }
        __syncthreads();
    }
    float mu = r1[0] * (1.f / 512.f);
    float var = r2[0] * (1.f / 512.f) - mu * mu;
    float rstd = rsqrtf(var + 1e-5f);
    g_xn[b * 512 + t] = (x0 - mu) * rstd;
    g_xn[b * 512 + t + 256] = (x1 - mu) * rstd;
}

// ---- K3: qh partials (K split x4) ----
__global__ __launch_bounds__(128) void k_qh4(const float* __restrict__ Wq,
                                             const float* __restrict__ lng,
                                             const float* __restrict__ lnb) {
    int kt = blockIdx.x, e = blockIdx.y, ks = blockIdx.z, t = threadIdx.x;
    __shared__ __align__(16) float qsm[128][16];
    int d0 = ks * 128;
    for (int idx = t; idx < 2048; idx += 128) {
        int d = idx >> 4, b = idx & 15;
        int gd = e * 512 + d0 + d;
        qsm[d][b] = g_xn[b * 512 + d0 + d] * lng[gd] + lnb[gd];
    }
    __syncthreads();
    int k = kt * 128 + t;
    ull acc[8] = {};
    const float* w = Wq + (size_t)e * 262144 + (size_t)d0 * 512 + k;
    #pragma unroll 8
    for (int d = 0; d < 128; d++) {
        ull wp = pack2(w[d * 512]);
        #pragma unroll
        for (int j = 0; j < 8; j++) ffma2(acc[j], *(const ull*)&qsm[d][2 * j], wp);
    }
    #pragma unroll
    for (int j = 0; j < 8; j++) {
        g_qp[((size_t)(ks * 16 + 2 * j) * 8 + e) * 512 + k] = lo32(acc[j]);
        g_qp[((size_t)(ks * 16 + 2 * j + 1) * 8 + e) * 512 + k] = hi32(acc[j]);
    }
}

// ---- K4: KQ (coalesced smem-transposed Wk; folds bq + qp reduce) ----
__global__ __launch_bounds__(128) void k_KQt(const float* __restrict__ Wk,
                                             const float* __restrict__ bq) {
    int dt = blockIdx.x, h = blockIdx.y, e = blockIdx.z, t = threadIdx.x;
    int d0 = dt * 128;
    __shared__ float wt[128][65];
    __shared__ __align__(16) float qs[64][16];
    #pragma unroll
    for (int it = 0; it < 64; it++) {
        int idx = t + it * 128;
        int row = idx >> 6, c = idx & 63;
        wt[row][c] = Wk[((size_t)e * 512 + d0 + row) * 512 + h * 64 + c];
    }
    #pragma unroll
    for (int it = 0; it < 8; it++) {
        int idx = t + it * 128;
        int c = idx >> 4, b = idx & 15;
        float s = bq[e * 512 + h * 64 + c];
        #pragma unroll
        for (int ks = 0; ks < 4; ks++)
            s += g_qp[((size_t)(ks * 16 + b) * 8 + e) * 512 + h * 64 + c];
        qs[c][b] = s;
    }
    __syncthreads();
    ull acc[8] = {};
    #pragma unroll 8
    for (int c = 0; c < 64; c++) {
        ull wp = pack2(wt[t][c]);
        #pragma unroll
        for (int j = 0; j < 8; j++) ffma2(acc[j], *(const ull*)&qs[c][2 * j], wp);
    }
    int eh = e * 8 + h;
    #pragma unroll
    for (int j = 0; j < 8; j++) {
        g_KQ[((size_t)(2 * j) * 64 + eh) * 512 + d0 + t] = lo32(acc[j]) * 0.125f;
        g_KQ[((size_t)(2 * j + 1) * 64 + eh) * 512 + d0 + t] = hi32(acc[j]) * 0.125f;
    }
}

// ---- K5: score partials (D split x2) ----
__global__ __launch_bounds__(128) void k_scores2(const float* __restrict__ retr) {
    int b = blockIdx.y, l0 = blockIdx.x * 128, ds = blockIdx.z, t = threadIdx.x;
    float* outbuf = ds ? g_sc1 : g_sc0;
    int dbase = ds * 256;
    __shared__ float rs[128][33];
    __shared__ __align__(16) float ksm[32][66];
    int lb = (t >> 3) * 8, ehb = (t & 7) * 8;
    ull acc[8][4] = {};
    for (int d0 = 0; d0 < 256; d0 += 32) {
        for (int idx = t; idx < 4096; idx += 128) {
            int l = idx >> 5, dd = idx & 31;
            rs[l][dd] = retr[((size_t)b * 2048 + l0 + l) * 512 + dbase + d0 + dd];
        }
        for (int idx = t; idx < 2048; idx += 128) {
            int eh = idx >> 5, dd = idx & 31;
            ksm[dd][eh] = g_KQ[(b * 64 + eh) * 512 + dbase + d0 + dd];
        }
        __syncthreads();
        #pragma unroll 2
        for (int dd = 0; dd < 32; dd++) {
            ull kp[4];
            #pragma unroll
            for (int j = 0; j < 4; j++) kp[j] = *(const ull*)&ksm[dd][ehb + 2 * j];
            #pragma unroll
            for (int i = 0; i < 8; i++) {
                ull rp = pack2(rs[lb + i][dd]);
                #pragma unroll
                for (int j = 0; j < 4; j++) ffma2(acc[i][j], rp, kp[j]);
            }
        }
        __syncthreads();
    }
    #pragma unroll
    for (int i = 0; i < 8; i++) {
        int l = l0 + lb + i;
        #pragma unroll
        for (int j = 0; j < 4; j++) {
            outbuf[(b * 64 + ehb + 2 * j) * 2048 + l] = lo32(acc[i][j]);
            outbuf[(b * 64 + ehb + 2 * j + 1) * 2048 + l] = hi32(acc[i][j]);
        }
    }
}

// ---- K6: sum partials + softmax ----
__global__ void k_softmax() {
    int id = blockIdx.x, t = threadIdx.x;
    const float* row0 = g_sc0 + (size_t)id * 2048;
    const float* row1 = g_sc1 + (size_t)id * 2048;
    float* row = g_scores + (size_t)id * 2048;
    __shared__ float red[256];
    float v[8];
    float m = -1e30f;
    for (int i = 0; i < 8; i++) {
        v[i] = row0[t + 256 * i] + row1[t + 256 * i];
        m = fmaxf(m, v[i]);
    }
    red[t] = m;
    __syncthreads();
    for (int s = 128; s > 0; s >>= 1) {
        if (t < s) red[t] = fmaxf(red[t], red[t + s]);
        __syncthreads();
    }
    m = red[0];
    __syncthreads();
    float z = 0.f;
    for (int i = 0; i < 8; i++) {
        v[i] = __expf(v[i] - m);
        z += v[i];
    }
    red[t] = z;
    __syncthreads();
    for (int s = 128; s > 0; s >>= 1) {
        if (t < s) red[t] += red[t + s];
        __syncthreads();
    }
    float rz = 1.f / red[0];
    for (int i = 0; i < 8; i++) row[t + 256 * i] = v[i] * rz;
}

// ---- entropy ----
__global__ void k_entropy() {
    int e = blockIdx.x, b = blockIdx.y, t = threadIdx.x;
    __shared__ float red[256];
    float acc = 0.f;
    for (int i = 0; i < 8; i++) {
        int l = t + i * 256;
        float p = 0.f;
        #pragma unroll
        for (int h = 0; h < 8; h++)
            p += g_scores[((size_t)b * 64 + e * 8 + h) * 2048 + l];
        p *= 0.125f;
        p = fmaxf(p, 1e-12f);
        acc -= p * __logf(p);
    }
    red[t] = acc;
    __syncthreads();
    for (int s = 128; s > 0; s >>= 1) {
        if (t < s) red[t] += red[t + s];
        __syncthreads();
    }
    if (t == 0) g_hent[b * 8 + e] = red[0];
}

// ---- K7: r partials (d-tile 256 x2, L split x4; 256 threads) ----
__global__ __launch_bounds__(256) void k_r2d(const float* __restrict__ retr) {
    int dt = blockIdx.x, b = blockIdx.y, ls = blockIdx.z, t = threadIdx.x;
    int d0 = dt * 256, lbase = ls * 512;
    __shared__ __align__(16) float rs[32][258];
    __shared__ float ps[64][33];
    int ehb = (t >> 4) * 4, dg = t & 15;
    ull acc[4][8] = {};
    for (int l0 = 0; l0 < 512; l0 += 32) {
        for (int idx = t; idx < 8192; idx += 256) {
            int l = idx >> 8, dd = idx & 255;
            rs[l][dd] = retr[((size_t)b * 2048 + lbase + l0 + l) * 512 + d0 + dd];
        }
        for (int idx = t; idx < 2048; idx += 256) {
            int eh = idx >> 5, ll = idx & 31;
            ps[eh][ll] = g_scores[(b * 64 + eh) * 2048 + lbase + l0 + ll];
        }
        __syncthreads();
        #pragma unroll 2
        for (int ll = 0; ll < 32; ll++) {
            ull rp[8];
            #pragma unroll
            for (int j = 0; j < 8; j++) rp[j] = *(const ull*)&rs[ll][dg * 2 + j * 32];
            #pragma unroll
            for (int i = 0; i < 4; i++) {
                ull pp = pack2(ps[ehb + i][ll]);
                #pragma unroll
                for (int j = 0; j < 8; j++) ffma2(acc[i][j], pp, rp[j]);
            }
        }
        __syncthreads();
    }
    #pragma unroll
    for (int i = 0; i < 4; i++)
        #pragma unroll
        for (int j = 0; j < 8; j++) {
            float2 v = make_float2(lo32(acc[i][j]), hi32(acc[i][j]));
            *(float2*)&g_rp[((size_t)ls * 524288) + ((size_t)b * 64 + ehb + i) * 512 + d0 + dg * 2 + j * 32] = v;
        }
}

// ---- K8: attn partials (K split x8; folds r-partial reduction) ----
__global__ __launch_bounds__(128) void k_attn8(const float* __restrict__ Wv) {
    int kt = blockIdx.x, e = blockIdx.y, ks = blockIdx.z, t = threadIdx.x;
    int k = kt * 128 + t, h0 = kt * 2, hl = t >> 6;
    __shared__ __align__(16) float rsm[64][2][16];
    int d0 = ks * 64;
    for (int idx = t; idx < 2048; idx += 128) {
        int dd = idx >> 5, rrem = idx & 31;
        int hl2 = rrem >> 4, bb = rrem & 15;
        size_t base = ((size_t)bb * 64 + e * 8 + h0 + hl2) * 512 + d0 + dd;
        rsm[dd][hl2][bb] = g_rp[base] + g_rp[524288 + base]
                         + g_rp[1048576 + base] + g_rp[1572864 + base];
    }
    __syncthreads();
    ull acc[8] = {};
    const float* w = Wv + (size_t)e * 262144 + (size_t)d0 * 512 + k;
    #pragma unroll 8
    for (int dd = 0; dd < 64; dd++) {
        ull wp = pack2(w[dd * 512]);
        #pragma unroll
        for (int j = 0; j < 8; j++) ffma2(acc[j], *(const ull*)&rsm[dd][hl][2 * j], wp);
    }
    #pragma unroll
    for (int j = 0; j < 8; j++) {
        g_ap[((size_t)(ks * 16 + 2 * j) * 8 + e) * 512 + k] = lo32(acc[j]);
        g_ap[((size_t)(ks * 16 + 2 * j + 1) * 8 + e) * 512 + k] = hi32(acc[j]);
    }
}

// ---- K9: wo partials (K split x4; folds bv + ap reduction) ----
__global__ __launch_bounds__(128) void k_wo4(const float* __restrict__ Wo,
                                             const float* __restrict__ bv) {
    int kt = blockIdx.x, e = blockIdx.y, ks = blockIdx.z, t = threadIdx.x;
    __shared__ __align__(16) float asm_[128][16];
    int d0 = ks * 128;
    for (int idx = t; idx < 2048; idx += 128) {
        int d = idx >> 4, b = idx & 15;
        float s = bv[e * 512 + d0 + d];
        #pragma unroll
        for (int kz = 0; kz < 8; kz++)
            s += g_ap[((size_t)(kz * 16 + b) * 8 + e) * 512 + d0 + d];
        asm_[d][b] = s;
    }
    __syncthreads();
    int k = kt * 128 + t;
    ull acc[8] = {};
    const float* w = Wo + (size_t)e * 262144 + (size_t)d0 * 512 + k;
    #pragma unroll 8
    for (int d = 0; d < 128; d++) {
        ull wp = pack2(w[d * 512]);
        #pragma unroll
        for (int j = 0; j < 8; j++) ffma2(acc[j], *(const ull*)&asm_[d][2 * j], wp);
    }
    #pragma unroll
    for (int j = 0; j < 8; j++) {
        g_op[((size_t)(ks * 16 + 2 * j) * 8 + e) * 512 + k] = lo32(acc[j]);
        g_op[((size_t)(ks * 16 + 2 * j + 1) * 8 + e) * 512 + k] = hi32(acc[j]);
    }
}

// ---- K10: reduce op + bo + residual, then LN -> x, xo (fused) ----
__global__ void k_bo_lno(const float* __restrict__ bo, const float* __restrict__ q,
                         const float* __restrict__ lng, const float* __restrict__ lnb) {
    int e = blockIdx.x, b = blockIdx.y, t = threadIdx.x;
    float xv[2];
    #pragma unroll
    for (int half = 0; half < 2; half++) {
        int col = t + half * 256;
        float s = bo[e * 512 + col] + q[b * 512 + col];
        #pragma unroll
        for (int ks = 0; ks < 4; ks++)
            s += g_op[((size_t)(ks * 16 + b) * 8 + e) * 512 + col];
        g_x[((size_t)b * 8 + e) * 512 + col] = s;
        xv[half] = s;
    }
    __shared__ float r1[256], r2[256];
    r1[t] = xv[0] + xv[1]; r2[t] = xv[0] * xv[0] + xv[1] * xv[1];
    __syncthreads();
    for (int s = 128; s > 0; s >>= 1) {
        if (t < s) { r1[t] += r1[t + s]; r2[t] += r2[t + s]; }
        __syncthreads();
    }
    float mu = r1[0] * (1.f / 512.f);
    float var = r2[0] * (1.f / 512.f) - mu * mu;
    float rstd = rsqrtf(var + 1e-5f);
    float* o = g_xo + ((size_t)b * 8 + e) * 512;
    o[t] = (xv[0] - mu) * rstd * lng[e * 512 + t] + lnb[e * 512 + t];
    o[t + 256] = (xv[1] - mu) * rstd * lng[e * 512 + t + 256] + lnb[e * 512 + t + 256];
}

// ---- K11: ffn1 partials (K split x4, unroll 4) ----
__global__ __launch_bounds__(128) void k_ffn14(const float* __restrict__ W1) {
    int ft = blockIdx.x * 256, e = blockIdx.y, ks = blockIdx.z, t = threadIdx.x;
    __shared__ __align__(16) float xsm[128][16];
    int d0 = ks * 128;
    for (int idx = t; idx < 2048; idx += 128) {
        int d = idx >> 4, b = idx & 15;
        xsm[d][b] = g_xo[((size_t)b * 8 + e) * 512 + d0 + d];
    }
    __syncthreads();
    int f0 = ft + t * 2;
    ull acc[2][8] = {};
    const float* w = W1 + (size_t)e * 1048576 + (size_t)d0 * 2048 + f0;
    #pragma unroll 4
    for (int d = 0; d < 128; d++) {
        float2 wv = *(const float2*)&w[(size_t)d * 2048];
        ull wp0 = pack2(wv.x), wp1 = pack2(wv.y);
        #pragma unroll
        for (int j = 0; j < 8; j++) {
            ull q2 = *(const ull*)&xsm[d][2 * j];
            ffma2(acc[0][j], q2, wp0);
            ffma2(acc[1][j], q2, wp1);
        }
    }
    #pragma unroll
    for (int s = 0; s < 2; s++)
        #pragma unroll
        for (int j = 0; j < 8; j++) {
            g_h1p[((size_t)(ks * 16 + 2 * j) * 8 + e) * 2048 + f0 + s] = lo32(acc[s][j]);
            g_h1p[((size_t)(ks * 16 + 2 * j + 1) * 8 + e) * 2048 + f0 + s] = hi32(acc[s][j]);
        }
}

// ---- K12: ffn2 partials (K split x8; folds b1 + gelu into staging) ----
__global__ __launch_bounds__(128) void k_ffn28(const float* __restrict__ W2,
                                               const float* __restrict__ b1) {
    int dt = blockIdx.x, e = blockIdx.y, ks = blockIdx.z, t = threadIdx.x;
    __shared__ __align__(16) float hsm[256][16];
    for (int idx = t; idx < 4096; idx += 128) {
        int k = idx >> 4, b = idx & 15;
        int col = ks * 256 + k;
        float s = b1[e * 2048 + col];
        #pragma unroll
        for (int j = 0; j < 4; j++)
            s += g_h1p[((size_t)(j * 16 + b) * 8 + e) * 2048 + col];
        hsm[k][b] = 0.5f * s * (1.f + erff(s * 0.70710678118654752f));
    }
    __syncthreads();
    int d = dt * 128 + t;
    ull acc[8] = {};
    const float* w = W2 + (size_t)e * 1048576 + (size_t)ks * 256 * 512 + d;
    #pragma unroll 8
    for (int k = 0; k < 256; k++) {
        ull wp = pack2(w[(size_t)k * 512]);
        #pragma unroll
        for (int j = 0; j < 8; j++) ffma2(acc[j], *(const ull*)&hsm[k][2 * j], wp);
    }
    #pragma unroll
    for (int j = 0; j < 8; j++) {
        g_yp[((size_t)(ks * 16 + 2 * j) * 8 + e) * 512 + d] = lo32(acc[j]);
        g_yp[((size_t)(ks * 16 + 2 * j + 1) * 8 + e) * 512 + d] = hi32(acc[j]);
    }
}

// ---- K14: combine ----
__global__ void k_final(const float* __restrict__ b2, float* __restrict__ out_f,
                        float* __restrict__ out_y, float* __restrict__ out_gt,
                        int write_full) {
    int b = blockIdx.x, t = threadIdx.x;
    __shared__ float gts[8];
    __shared__ float ssum;
    if (t < 8) gts[t] = g_gates[b * 8 + t] * __expf(-0.5f * g_hent[b * 8 + t]);
    __syncthreads();
    if (t == 0) {
        float s = 0.f;
        for (int i = 0; i < 8; i++) s += gts[i];
        ssum = 1.f / (s + 1e-9f);
    }
    __syncthreads();
    float rz = ssum;
    int d = t;
    float fused = 0.f;
    #pragma unroll
    for (int e = 0; e < 8; e++) {
        float yv = g_x[(b * 8 + e) * 512 + d] + b2[e * 512 + d];
        #pragma unroll
        for (int ks = 0; ks < 8; ks++)
            yv += g_yp[(((size_t)ks * 16 + b) * 8 + e) * 512 + d];
        fused += gts[e] * rz * yv;
        if (write_full) out_y[((size_t)b * 8 + e) * 512 + d] = yv;
    }
    out_f[b * 512 + d] = fused;
    if (write_full && t < 8) out_gt[b * 8 + t] = gts[t] * rz;
}

extern "C" void kernel_launch(void* const* d_in, const int* in_sizes, int n_in,
                              void* d_out, int out_size) {
    const float* query = (const float*)d_in[0];
    const float* retrieved = (const float*)d_in[1];
    const float* w_gate = (const float*)d_in[2];
    const float* ln_q_g = (const float*)d_in[3];
    const float* ln_q_b = (const float*)d_in[4];
    const float* Wq = (const float*)d_in[5];
    const float* bq = (const float*)d_in[6];
    const float* Wk = (const float*)d_in[7];
    const float* Wv = (const float*)d_in[9];
    const float* bv = (const float*)d_in[10];
    const float* Wo = (const float*)d_in[11];
    const float* bo = (const float*)d_in[12];
    const float* ln_o_g = (const float*)d_in[13];
    const float* ln_o_b = (const float*)d_in[14];
    const float* W1 = (const float*)d_in[15];
    const float* b1 = (const float*)d_in[16];
    const float* W2 = (const float*)d_in[17];
    const float* b2 = (const float*)d_in[18];

    float* out = (float*)d_out;
    int write_full = (out_size >= 8192 + 65536 + 128) ? 1 : 0;
    float* out_f = out;
    float* out_y = write_full ? out + 8192 : out;
    float* out_gt = write_full ? out + 8192 + 65536 : out;

    k_gates<<<16, 256>>>(query, w_gate);
    k_lnq<<<16, 256>>>(query);
    k_qh4<<<dim3(4, 8, 4), 128>>>(Wq, ln_q_g, ln_q_b);
    k_KQt<<<dim3(4, 8, 8), 128>>>(Wk, bq);
    k_scores2<<<dim3(16, 16, 2), 128>>>(retrieved);
    k_softmax<<<1024, 256>>>();
    k_entropy<<<dim3(8, 16), 256>>>();
    k_r2d<<<dim3(2, 16, 4), 256>>>(retrieved);
    k_attn8<<<dim3(4, 8, 8), 128>>>(Wv);
    k_wo4<<<dim3(4, 8, 4), 128>>>(Wo, bv);
    k_bo_lno<<<dim3(8, 16), 256>>>(bo, query, ln_o_g, ln_o_b);
    k_ffn14<<<dim3(8, 8, 4), 128>>>(W1);
    k_ffn28<<<dim3(4, 8, 8), 128>>>(W2, b1);
    k_final<<<16, 512>>>(b2, out_f, out_y, out_gt, write_full);
}

// round 14
// speedup vs baseline: 1.0341x; 1.0341x over previous
#include <cuda_runtime.h>
#include <math.h>

// B=16, L=2048, D=512, E=8, H=8, HD=64, F=2048
typedef unsigned long long ull;

__device__ float g_gates[128];
__device__ float g_hent[128];
__device__ float g_xn[16 * 512];
__device__ __align__(16) float g_qp[4 * 16 * 8 * 512];
__device__ __align__(16) float g_KQ[16 * 64 * 512];
__device__ __align__(16) float g_sc0[16 * 64 * 2048];
__device__ __align__(16) float g_sc1[16 * 64 * 2048];
__device__ __align__(16) float g_scores[16 * 64 * 2048];
__device__ __align__(16) float g_rp[4 * 16 * 64 * 512];
__device__ __align__(16) float g_ap[8 * 16 * 8 * 512];
__device__ __align__(16) float g_op[8 * 16 * 8 * 512];
__device__ __align__(16) float g_x[16 * 8 * 512];
__device__ __align__(16) float g_xo[16 * 8 * 512];
__device__ __align__(16) float g_h1p[4 * 16 * 8 * 2048];
__device__ __align__(16) float g_yp[8 * 16 * 8 * 512];

__device__ __forceinline__ ull pack2(float x) {
    ull r; unsigned u = __float_as_uint(x);
    asm("mov.b64 %0, {%1, %1};" : "=l"(r) : "r"(u));
    return r;
}
__device__ __forceinline__ void ffma2(ull& d, ull a, ull b) {
    asm("fma.rn.f32x2 %0, %1, %2, %0;" : "+l"(d) : "l"(a), "l"(b));
}
__device__ __forceinline__ float lo32(ull v) { return __uint_as_float((unsigned)v); }
__device__ __forceinline__ float hi32(ull v) { return __uint_as_float((unsigned)(v >> 32)); }

// ---- K1: gates ----
__global__ void k_gates(const float* __restrict__ q, const float* __restrict__ wg) {
    int b = blockIdx.x, t = threadIdx.x;
    __shared__ float part[256];
    int e = t & 7, chunk = t >> 3;
    float s = 0.f;
    for (int i = 0; i < 16; i++) {
        int d = chunk * 16 + i;
        s += q[b * 512 + d] * wg[d * 8 + e];
    }
    part[t] = s;
    __syncthreads();
    for (int st = 128; st >= 8; st >>= 1) {
        if (t < st) part[t] += part[t + st];
        __syncthreads();
    }
    if (t == 0) {
        float m = part[0];
        for (int i = 1; i < 8; i++) m = fmaxf(m, part[i]);
        float z = 0.f, ex[8];
        for (int i = 0; i < 8; i++) { ex[i] = __expf(part[i] - m); z += ex[i]; }
        float rz = 1.f / z;
        for (int i = 0; i < 8; i++) g_gates[b * 8 + i] = ex[i] * rz;
    }
}

// ---- K2: LN(query) -> xn ----
__global__ void k_lnq(const float* __restrict__ q) {
    int b = blockIdx.x, t = threadIdx.x;
    __shared__ float r1[256], r2[256];
    float x0 = q[b * 512 + t], x1 = q[b * 512 + t + 256];
    r1[t] = x0 + x1; r2[t] = x0 * x0 + x1 * x1;
    __syncthreads();
    for (int s = 128; s > 0; s >>= 1) {
        if (t < s) { r1[t] += r1[t + s]; r2[t] += r2[t + s]; }
        __syncthreads();
    }
    float mu = r1[0] * (1.f / 512.f);
    float var = r2[0] * (1.f / 512.f) - mu * mu;
    float rstd = rsqrtf(var + 1e-5f);
    g_xn[b * 512 + t] = (x0 - mu) * rstd;
    g_xn[b * 512 + t + 256] = (x1 - mu) * rstd;
}

// ---- K3: qh partials (K split x4) ----
__global__ __launch_bounds__(128) void k_qh4(const float* __restrict__ Wq,
                                             const float* __restrict__ lng,
                                             const float* __restrict__ lnb) {
    int kt = blockIdx.x, e = blockIdx.y, ks = blockIdx.z, t = threadIdx.x;
    __shared__ __align__(16) float qsm[128][16];
    int d0 = ks * 128;
    for (int idx = t; idx < 2048; idx += 128) {
        int d = idx >> 4, b = idx & 15;
        int gd = e * 512 + d0 + d;
        qsm[d][b] = g_xn[b * 512 + d0 + d] * lng[gd] + lnb[gd];
    }
    __syncthreads();
    int k = kt * 128 + t;
    ull acc[8] = {};
    const float* w = Wq + (size_t)e * 262144 + (size_t)d0 * 512 + k;
    #pragma unroll 8
    for (int d = 0; d < 128; d++) {
        ull wp = pack2(w[d * 512]);
        #pragma unroll
        for (int j = 0; j < 8; j++) ffma2(acc[j], *(const ull*)&qsm[d][2 * j], wp);
    }
    #pragma unroll
    for (int j = 0; j < 8; j++) {
        g_qp[((size_t)(ks * 16 + 2 * j) * 8 + e) * 512 + k] = lo32(acc[j]);
        g_qp[((size_t)(ks * 16 + 2 * j + 1) * 8 + e) * 512 + k] = hi32(acc[j]);
    }
}

// ---- K4: KQ (coalesced smem-transposed Wk; folds bq + qp reduce) ----
__global__ __launch_bounds__(128) void k_KQt(const float* __restrict__ Wk,
                                             const float* __restrict__ bq) {
    int dt = blockIdx.x, h = blockIdx.y, e = blockIdx.z, t = threadIdx.x;
    int d0 = dt * 128;
    __shared__ float wt[128][65];
    __shared__ __align__(16) float qs[64][16];
    #pragma unroll
    for (int it = 0; it < 64; it++) {
        int idx = t + it * 128;
        int row = idx >> 6, c = idx & 63;
        wt[row][c] = Wk[((size_t)e * 512 + d0 + row) * 512 + h * 64 + c];
    }
    #pragma unroll
    for (int it = 0; it < 8; it++) {
        int idx = t + it * 128;
        int c = idx >> 4, b = idx & 15;
        float s = bq[e * 512 + h * 64 + c];
        #pragma unroll
        for (int ks = 0; ks < 4; ks++)
            s += g_qp[((size_t)(ks * 16 + b) * 8 + e) * 512 + h * 64 + c];
        qs[c][b] = s;
    }
    __syncthreads();
    ull acc[8] = {};
    #pragma unroll 8
    for (int c = 0; c < 64; c++) {
        ull wp = pack2(wt[t][c]);
        #pragma unroll
        for (int j = 0; j < 8; j++) ffma2(acc[j], *(const ull*)&qs[c][2 * j], wp);
    }
    int eh = e * 8 + h;
    #pragma unroll
    for (int j = 0; j < 8; j++) {
        g_KQ[((size_t)(2 * j) * 64 + eh) * 512 + d0 + t] = lo32(acc[j]) * 0.125f;
        g_KQ[((size_t)(2 * j + 1) * 64 + eh) * 512 + d0 + t] = hi32(acc[j]) * 0.125f;
    }
}

// ---- K5: score partials (D split x2) ----
__global__ __launch_bounds__(128) void k_scores2(const float* __restrict__ retr) {
    int b = blockIdx.y, l0 = blockIdx.x * 128, ds = blockIdx.z, t = threadIdx.x;
    float* outbuf = ds ? g_sc1 : g_sc0;
    int dbase = ds * 256;
    __shared__ float rs[128][33];
    __shared__ __align__(16) float ksm[32][66];
    int lb = (t >> 3) * 8, ehb = (t & 7) * 8;
    ull acc[8][4] = {};
    for (int d0 = 0; d0 < 256; d0 += 32) {
        for (int idx = t; idx < 4096; idx += 128) {
            int l = idx >> 5, dd = idx & 31;
            rs[l][dd] = retr[((size_t)b * 2048 + l0 + l) * 512 + dbase + d0 + dd];
        }
        for (int idx = t; idx < 2048; idx += 128) {
            int eh = idx >> 5, dd = idx & 31;
            ksm[dd][eh] = g_KQ[(b * 64 + eh) * 512 + dbase + d0 + dd];
        }
        __syncthreads();
        #pragma unroll 2
        for (int dd = 0; dd < 32; dd++) {
            ull kp[4];
            #pragma unroll
            for (int j = 0; j < 4; j++) kp[j] = *(const ull*)&ksm[dd][ehb + 2 * j];
            #pragma unroll
            for (int i = 0; i < 8; i++) {
                ull rp = pack2(rs[lb + i][dd]);
                #pragma unroll
                for (int j = 0; j < 4; j++) ffma2(acc[i][j], rp, kp[j]);
            }
        }
        __syncthreads();
    }
    #pragma unroll
    for (int i = 0; i < 8; i++) {
        int l = l0 + lb + i;
        #pragma unroll
        for (int j = 0; j < 4; j++) {
            outbuf[(b * 64 + ehb + 2 * j) * 2048 + l] = lo32(acc[i][j]);
            outbuf[(b * 64 + ehb + 2 * j + 1) * 2048 + l] = hi32(acc[i][j]);
        }
    }
}

// ---- K6: sum partials + softmax ----
__global__ void k_softmax() {
    int id = blockIdx.x, t = threadIdx.x;
    const float* row0 = g_sc0 + (size_t)id * 2048;
    const float* row1 = g_sc1 + (size_t)id * 2048;
    float* row = g_scores + (size_t)id * 2048;
    __shared__ float red[256];
    float v[8];
    float m = -1e30f;
    for (int i = 0; i < 8; i++) {
        v[i] = row0[t + 256 * i] + row1[t + 256 * i];
        m = fmaxf(m, v[i]);
    }
    red[t] = m;
    __syncthreads();
    for (int s = 128; s > 0; s >>= 1) {
        if (t < s) red[t] = fmaxf(red[t], red[t + s]);
        __syncthreads();
    }
    m = red[0];
    __syncthreads();
    float z = 0.f;
    for (int i = 0; i < 8; i++) {
        v[i] = __expf(v[i] - m);
        z += v[i];
    }
    red[t] = z;
    __syncthreads();
    for (int s = 128; s > 0; s >>= 1) {
        if (t < s) red[t] += red[t + s];
        __syncthreads();
    }
    float rz = 1.f / red[0];
    for (int i = 0; i < 8; i++) row[t + 256 * i] = v[i] * rz;
}

// ---- entropy ----
__global__ void k_entropy() {
    int e = blockIdx.x, b = blockIdx.y, t = threadIdx.x;
    __shared__ float red[256];
    float acc = 0.f;
    for (int i = 0; i < 8; i++) {
        int l = t + i * 256;
        float p = 0.f;
        #pragma unroll
        for (int h = 0; h < 8; h++)
            p += g_scores[((size_t)b * 64 + e * 8 + h) * 2048 + l];
        p *= 0.125f;
        p = fmaxf(p, 1e-12f);
        acc -= p * __logf(p);
    }
    red[t] = acc;
    __syncthreads();
    for (int s = 128; s > 0; s >>= 1) {
        if (t < s) red[t] += red[t + s];
        __syncthreads();
    }
    if (t == 0) g_hent[b * 8 + e] = red[0];
}

// ---- K7: r partials (L split x4; d-tile 64) ----
__global__ __launch_bounds__(128) void k_r4(const float* __restrict__ retr) {
    int d0 = blockIdx.x * 64, b = blockIdx.y, ls = blockIdx.z, t = threadIdx.x;
    int lbase = ls * 512;
    __shared__ __align__(16) float rs[32][66];
    __shared__ float ps[64][33];
    int ehb = (t >> 3) * 4, dgb = (t & 7) * 8;
    ull acc[4][4] = {};
    for (int l0 = 0; l0 < 512; l0 += 32) {
        for (int idx = t; idx < 2048; idx += 128) {
            int l = idx >> 6, dd = idx & 63;
            rs[l][dd] = retr[((size_t)b * 2048 + lbase + l0 + l) * 512 + d0 + dd];
        }
        for (int idx = t; idx < 2048; idx += 128) {
            int eh = idx >> 5, ll = idx & 31;
            ps[eh][ll] = g_scores[(b * 64 + eh) * 2048 + lbase + l0 + ll];
        }
        __syncthreads();
        #pragma unroll 2
        for (int ll = 0; ll < 32; ll++) {
            ull rp[4];
            #pragma unroll
            for (int j = 0; j < 4; j++) rp[j] = *(const ull*)&rs[ll][dgb + 2 * j];
            #pragma unroll
            for (int i = 0; i < 4; i++) {
                ull pp = pack2(ps[ehb + i][ll]);
                #pragma unroll
                for (int j = 0; j < 4; j++) ffma2(acc[i][j], pp, rp[j]);
            }
        }
        __syncthreads();
    }
    #pragma unroll
    for (int i = 0; i < 4; i++)
        #pragma unroll
        for (int j = 0; j < 4; j++) {
            float2 v = make_float2(lo32(acc[i][j]), hi32(acc[i][j]));
            *(float2*)&g_rp[((size_t)ls * 524288) + ((size_t)b * 64 + ehb + i) * 512 + d0 + dgb + 2 * j] = v;
        }
}

// ---- K8: attn partials (K split x8; folds r-partial reduction) ----
__global__ __launch_bounds__(128) void k_attn8(const float* __restrict__ Wv) {
    int kt = blockIdx.x, e = blockIdx.y, ks = blockIdx.z, t = threadIdx.x;
    int k = kt * 128 + t, h0 = kt * 2, hl = t >> 6;
    __shared__ __align__(16) float rsm[64][2][16];
    int d0 = ks * 64;
    for (int idx = t; idx < 2048; idx += 128) {
        int dd = idx >> 5, rrem = idx & 31;
        int hl2 = rrem >> 4, bb = rrem & 15;
        size_t base = ((size_t)bb * 64 + e * 8 + h0 + hl2) * 512 + d0 + dd;
        rsm[dd][hl2][bb] = g_rp[base] + g_rp[524288 + base]
                         + g_rp[1048576 + base] + g_rp[1572864 + base];
    }
    __syncthreads();
    ull acc[8] = {};
    const float* w = Wv + (size_t)e * 262144 + (size_t)d0 * 512 + k;
    #pragma unroll 8
    for (int dd = 0; dd < 64; dd++) {
        ull wp = pack2(w[dd * 512]);
        #pragma unroll
        for (int j = 0; j < 8; j++) ffma2(acc[j], *(const ull*)&rsm[dd][hl][2 * j], wp);
    }
    #pragma unroll
    for (int j = 0; j < 8; j++) {
        g_ap[((size_t)(ks * 16 + 2 * j) * 8 + e) * 512 + k] = lo32(acc[j]);
        g_ap[((size_t)(ks * 16 + 2 * j + 1) * 8 + e) * 512 + k] = hi32(acc[j]);
    }
}

// ---- K9: wo partials (K split x4; folds bv + ap reduction) ----
__global__ __launch_bounds__(128) void k_wo4(const float* __restrict__ Wo,
                                             const float* __restrict__ bv) {
    int kt = blockIdx.x, e = blockIdx.y, ks = blockIdx.z, t = threadIdx.x;
    __shared__ __align__(16) float asm_[128][16];
    int d0 = ks * 128;
    for (int idx = t; idx < 2048; idx += 128) {
        int d = idx >> 4, b = idx & 15;
        float s = bv[e * 512 + d0 + d];
        #pragma unroll
        for (int kz = 0; kz < 8; kz++)
            s += g_ap[((size_t)(kz * 16 + b) * 8 + e) * 512 + d0 + d];
        asm_[d][b] = s;
    }
    __syncthreads();
    int k = kt * 128 + t;
    ull acc[8] = {};
    const float* w = Wo + (size_t)e * 262144 + (size_t)d0 * 512 + k;
    #pragma unroll 8
    for (int d = 0; d < 128; d++) {
        ull wp = pack2(w[d * 512]);
        #pragma unroll
        for (int j = 0; j < 8; j++) ffma2(acc[j], *(const ull*)&asm_[d][2 * j], wp);
    }
    #pragma unroll
    for (int j = 0; j < 8; j++) {
        g_op[((size_t)(ks * 16 + 2 * j) * 8 + e) * 512 + k] = lo32(acc[j]);
        g_op[((size_t)(ks * 16 + 2 * j + 1) * 8 + e) * 512 + k] = hi32(acc[j]);
    }
}

// ---- K10: reduce op + bo + residual, then LN -> x, xo (fused) ----
__global__ void k_bo_lno(const float* __restrict__ bo, const float* __restrict__ q,
                         const float* __restrict__ lng, const float* __restrict__ lnb) {
    int e = blockIdx.x, b = blockIdx.y, t = threadIdx.x;
    float xv[2];
    #pragma unroll
    for (int half = 0; half < 2; half++) {
        int col = t + half * 256;
        float s = bo[e * 512 + col] + q[b * 512 + col];
        #pragma unroll
        for (int ks = 0; ks < 4; ks++)
            s += g_op[((size_t)(ks * 16 + b) * 8 + e) * 512 + col];
        g_x[((size_t)b * 8 + e) * 512 + col] = s;
        xv[half] = s;
    }
    __shared__ float r1[256], r2[256];
    r1[t] = xv[0] + xv[1]; r2[t] = xv[0] * xv[0] + xv[1] * xv[1];
    __syncthreads();
    for (int s = 128; s > 0; s >>= 1) {
        if (t < s) { r1[t] += r1[t + s]; r2[t] += r2[t + s]; }
        __syncthreads();
    }
    float mu = r1[0] * (1.f / 512.f);
    float var = r2[0] * (1.f / 512.f) - mu * mu;
    float rstd = rsqrtf(var + 1e-5f);
    float* o = g_xo + ((size_t)b * 8 + e) * 512;
    o[t] = (xv[0] - mu) * rstd * lng[e * 512 + t] + lnb[e * 512 + t];
    o[t + 256] = (xv[1] - mu) * rstd * lng[e * 512 + t + 256] + lnb[e * 512 + t + 256];
}

// ---- K11: ffn1 partials (K split x4, unroll 4) ----
__global__ __launch_bounds__(128) void k_ffn14(const float* __restrict__ W1) {
    int ft = blockIdx.x * 256, e = blockIdx.y, ks = blockIdx.z, t = threadIdx.x;
    __shared__ __align__(16) float xsm[128][16];
    int d0 = ks * 128;
    for (int idx = t; idx < 2048; idx += 128) {
        int d = idx >> 4, b = idx & 15;
        xsm[d][b] = g_xo[((size_t)b * 8 + e) * 512 + d0 + d];
    }
    __syncthreads();
    int f0 = ft + t * 2;
    ull acc[2][8] = {};
    const float* w = W1 + (size_t)e * 1048576 + (size_t)d0 * 2048 + f0;
    #pragma unroll 4
    for (int d = 0; d < 128; d++) {
        float2 wv = *(const float2*)&w[(size_t)d * 2048];
        ull wp0 = pack2(wv.x), wp1 = pack2(wv.y);
        #pragma unroll
        for (int j = 0; j < 8; j++) {
            ull q2 = *(const ull*)&xsm[d][2 * j];
            ffma2(acc[0][j], q2, wp0);
            ffma2(acc[1][j], q2, wp1);
        }
    }
    #pragma unroll
    for (int s = 0; s < 2; s++)
        #pragma unroll
        for (int j = 0; j < 8; j++) {
            g_h1p[((size_t)(ks * 16 + 2 * j) * 8 + e) * 2048 + f0 + s] = lo32(acc[s][j]);
            g_h1p[((size_t)(ks * 16 + 2 * j + 1) * 8 + e) * 2048 + f0 + s] = hi32(acc[s][j]);
        }
}

// ---- K12: ffn2 partials (K split x8; folds b1 + gelu into staging) ----
__global__ __launch_bounds__(128) void k_ffn28(const float* __restrict__ W2,
                                               const float* __restrict__ b1) {
    int dt = blockIdx.x, e = blockIdx.y, ks = blockIdx.z, t = threadIdx.x;
    __shared__ __align__(16) float hsm[256][16];
    for (int idx = t; idx < 4096; idx += 128) {
        int k = idx >> 4, b = idx & 15;
        int col = ks * 256 + k;
        float s = b1[e * 2048 + col];
        #pragma unroll
        for (int j = 0; j < 4; j++)
            s += g_h1p[((size_t)(j * 16 + b) * 8 + e) * 2048 + col];
        hsm[k][b] = 0.5f * s * (1.f + erff(s * 0.70710678118654752f));
    }
    __syncthreads();
    int d = dt * 128 + t;
    ull acc[8] = {};
    const float* w = W2 + (size_t)e * 1048576 + (size_t)ks * 256 * 512 + d;
    #pragma unroll 8
    for (int k = 0; k < 256; k++) {
        ull wp = pack2(w[(size_t)k * 512]);
        #pragma unroll
        for (int j = 0; j < 8; j++) ffma2(acc[j], *(const ull*)&hsm[k][2 * j], wp);
    }
    #pragma unroll
    for (int j = 0; j < 8; j++) {
        g_yp[((size_t)(ks * 16 + 2 * j) * 8 + e) * 512 + d] = lo32(acc[j]);
        g_yp[((size_t)(ks * 16 + 2 * j + 1) * 8 + e) * 512 + d] = hi32(acc[j]);
    }
}

// ---- K14: combine ----
__global__ void k_final(const float* __restrict__ b2, float* __restrict__ out_f,
                        float* __restrict__ out_y, float* __restrict__ out_gt,
                        int write_full) {
    int b = blockIdx.x, t = threadIdx.x;
    __shared__ float gts[8];
    __shared__ float ssum;
    if (t < 8) gts[t] = g_gates[b * 8 + t] * __expf(-0.5f * g_hent[b * 8 + t]);
    __syncthreads();
    if (t == 0) {
        float s = 0.f;
        for (int i = 0; i < 8; i++) s += gts[i];
        ssum = 1.f / (s + 1e-9f);
    }
    __syncthreads();
    float rz = ssum;
    int d = t;
    float fused = 0.f;
    #pragma unroll
    for (int e = 0; e < 8; e++) {
        float yv = g_x[(b * 8 + e) * 512 + d] + b2[e * 512 + d];
        #pragma unroll
        for (int ks = 0; ks < 8; ks++)
            yv += g_yp[(((size_t)ks * 16 + b) * 8 + e) * 512 + d];
        fused += gts[e] * rz * yv;
        if (write_full) out_y[((size_t)b * 8 + e) * 512 + d] = yv;
    }
    out_f[b * 512 + d] = fused;
    if (write_full && t < 8) out_gt[b * 8 + t] = gts[t] * rz;
}

extern "C" void kernel_launch(void* const* d_in, const int* in_sizes, int n_in,
                              void* d_out, int out_size) {
    const float* query = (const float*)d_in[0];
    const float* retrieved = (const float*)d_in[1];
    const float* w_gate = (const float*)d_in[2];
    const float* ln_q_g = (const float*)d_in[3];
    const float* ln_q_b = (const float*)d_in[4];
    const float* Wq = (const float*)d_in[5];
    const float* bq = (const float*)d_in[6];
    const float* Wk = (const float*)d_in[7];
    const float* Wv = (const float*)d_in[9];
    const float* bv = (const float*)d_in[10];
    const float* Wo = (const float*)d_in[11];
    const float* bo = (const float*)d_in[12];
    const float* ln_o_g = (const float*)d_in[13];
    const float* ln_o_b = (const float*)d_in[14];
    const float* W1 = (const float*)d_in[15];
    const float* b1 = (const float*)d_in[16];
    const float* W2 = (const float*)d_in[17];
    const float* b2 = (const float*)d_in[18];

    float* out = (float*)d_out;
    int write_full = (out_size >= 8192 + 65536 + 128) ? 1 : 0;
    float* out_f = out;
    float* out_y = write_full ? out + 8192 : out;
    float* out_gt = write_full ? out + 8192 + 65536 : out;

    k_gates<<<16, 256>>>(query, w_gate);
    k_lnq<<<16, 256>>>(query);
    k_qh4<<<dim3(4, 8, 4), 128>>>(Wq, ln_q_g, ln_q_b);
    k_KQt<<<dim3(4, 8, 8), 128>>>(Wk, bq);
    k_scores2<<<dim3(16, 16, 2), 128>>>(retrieved);
    k_softmax<<<1024, 256>>>();
    k_entropy<<<dim3(8, 16), 256>>>();
    k_r4<<<dim3(8, 16, 4), 128>>>(retrieved);
    k_attn8<<<dim3(4, 8, 8), 128>>>(Wv);
    k_wo4<<<dim3(4, 8, 4), 128>>>(Wo, bv);
    k_bo_lno<<<dim3(8, 16), 256>>>(bo, query, ln_o_g, ln_o_b);
    k_ffn14<<<dim3(8, 8, 4), 128>>>(W1);
    k_ffn28<<<dim3(4, 8, 8), 128>>>(W2, b1);
    k_final<<<16, 512>>>(b2, out_f, out_y, out_gt, write_full);
}

// round 16
// speedup vs baseline: 1.1844x; 1.1453x over previous
#include <cuda_runtime.h>
#include <math.h>

// B=16, L=2048, D=512, E=8, H=8, HD=64, F=2048
typedef unsigned long long ull;

__device__ float g_gates[128];
__device__ float g_hent[128];
__device__ float g_xn[16 * 512];
__device__ __align__(16) float g_qp[4 * 16 * 8 * 512];
__device__ __align__(16) float g_KQ[16 * 64 * 512];
__device__ __align__(16) float g_sc0[16 * 64 * 2048];
__device__ __align__(16) float g_sc1[16 * 64 * 2048];
__device__ __align__(16) float g_scores[16 * 64 * 2048];
__device__ __align__(16) float g_rp[4 * 16 * 64 * 512];
__device__ __align__(16) float g_ap[8 * 16 * 8 * 512];
__device__ __align__(16) float g_op[8 * 16 * 8 * 512];
__device__ __align__(16) float g_x[16 * 8 * 512];
__device__ __align__(16) float g_xo[16 * 8 * 512];
__device__ __align__(16) float g_h1p[4 * 16 * 8 * 2048];
__device__ __align__(16) float g_yp[16 * 16 * 8 * 512];

__device__ __forceinline__ ull pack2(float x) {
    ull r; unsigned u = __float_as_uint(x);
    asm("mov.b64 %0, {%1, %1};" : "=l"(r) : "r"(u));
    return r;
}
__device__ __forceinline__ void ffma2(ull& d, ull a, ull b) {
    asm("fma.rn.f32x2 %0, %1, %2, %0;" : "+l"(d) : "l"(a), "l"(b));
}
__device__ __forceinline__ float lo32(ull v) { return __uint_as_float((unsigned)v); }
__device__ __forceinline__ float hi32(ull v) { return __uint_as_float((unsigned)(v >> 32)); }

// ---- K1: gates ----
__global__ void k_gates(const float* __restrict__ q, const float* __restrict__ wg) {
    int b = blockIdx.x, t = threadIdx.x;
    __shared__ float part[256];
    int e = t & 7, chunk = t >> 3;
    float s = 0.f;
    for (int i = 0; i < 16; i++) {
        int d = chunk * 16 + i;
        s += q[b * 512 + d] * wg[d * 8 + e];
    }
    part[t] = s;
    __syncthreads();
    for (int st = 128; st >= 8; st >>= 1) {
        if (t < st) part[t] += part[t + st];
        __syncthreads();
    }
    if (t == 0) {
        float m = part[0];
        for (int i = 1; i < 8; i++) m = fmaxf(m, part[i]);
        float z = 0.f, ex[8];
        for (int i = 0; i < 8; i++) { ex[i] = __expf(part[i] - m); z += ex[i]; }
        float rz = 1.f / z;
        for (int i = 0; i < 8; i++) g_gates[b * 8 + i] = ex[i] * rz;
    }
}

// ---- K2: LN(query) -> xn ----
__global__ void k_lnq(const float* __restrict__ q) {
    int b = blockIdx.x, t = threadIdx.x;
    __shared__ float r1[256], r2[256];
    float x0 = q[b * 512 + t], x1 = q[b * 512 + t + 256];
    r1[t] = x0 + x1; r2[t] = x0 * x0 + x1 * x1;
    __syncthreads();
    for (int s = 128; s > 0; s >>= 1) {
        if (t < s) { r1[t] += r1[t + s]; r2[t] += r2[t + s]; }
        __syncthreads();
    }
    float mu = r1[0] * (1.f / 512.f);
    float var = r2[0] * (1.f / 512.f) - mu * mu;
    float rstd = rsqrtf(var + 1e-5f);
    g_xn[b * 512 + t] = (x0 - mu) * rstd;
    g_xn[b * 512 + t + 256] = (x1 - mu) * rstd;
}

// ---- K3: qh partials (K split x4) ----
__global__ __launch_bounds__(128) void k_qh4(const float* __restrict__ Wq,
                                             const float* __restrict__ lng,
                                             const float* __restrict__ lnb) {
    int kt = blockIdx.x, e = blockIdx.y, ks = blockIdx.z, t = threadIdx.x;
    __shared__ __align__(16) float qsm[128][16];
    int d0 = ks * 128;
    for (int idx = t; idx < 2048; idx += 128) {
        int d = idx >> 4, b = idx & 15;
        int gd = e * 512 + d0 + d;
        qsm[d][b] = g_xn[b * 512 + d0 + d] * lng[gd] + lnb[gd];
    }
    __syncthreads();
    int k = kt * 128 + t;
    ull acc[8] = {};
    const float* w = Wq + (size_t)e * 262144 + (size_t)d0 * 512 + k;
    #pragma unroll 8
    for (int d = 0; d < 128; d++) {
        ull wp = pack2(w[d * 512]);
        #pragma unroll
        for (int j = 0; j < 8; j++) ffma2(acc[j], *(const ull*)&qsm[d][2 * j], wp);
    }
    #pragma unroll
    for (int j = 0; j < 8; j++) {
        g_qp[((size_t)(ks * 16 + 2 * j) * 8 + e) * 512 + k] = lo32(acc[j]);
        g_qp[((size_t)(ks * 16 + 2 * j + 1) * 8 + e) * 512 + k] = hi32(acc[j]);
    }
}

// ---- K4: KQ (coalesced smem-transposed Wk; folds bq + qp reduce) ----
__global__ __launch_bounds__(128) void k_KQt(const float* __restrict__ Wk,
                                             const float* __restrict__ bq) {
    int dt = blockIdx.x, h = blockIdx.y, e = blockIdx.z, t = threadIdx.x;
    int d0 = dt * 128;
    __shared__ float wt[128][65];
    __shared__ __align__(16) float qs[64][16];
    #pragma unroll
    for (int it = 0; it < 64; it++) {
        int idx = t + it * 128;
        int row = idx >> 6, c = idx & 63;
        wt[row][c] = Wk[((size_t)e * 512 + d0 + row) * 512 + h * 64 + c];
    }
    #pragma unroll
    for (int it = 0; it < 8; it++) {
        int idx = t + it * 128;
        int c = idx >> 4, b = idx & 15;
        float s = bq[e * 512 + h * 64 + c];
        #pragma unroll
        for (int ks = 0; ks < 4; ks++)
            s += g_qp[((size_t)(ks * 16 + b) * 8 + e) * 512 + h * 64 + c];
        qs[c][b] = s;
    }
    __syncthreads();
    ull acc[8] = {};
    #pragma unroll 8
    for (int c = 0; c < 64; c++) {
        ull wp = pack2(wt[t][c]);
        #pragma unroll
        for (int j = 0; j < 8; j++) ffma2(acc[j], *(const ull*)&qs[c][2 * j], wp);
    }
    int eh = e * 8 + h;
    #pragma unroll
    for (int j = 0; j < 8; j++) {
        g_KQ[((size_t)(2 * j) * 64 + eh) * 512 + d0 + t] = lo32(acc[j]) * 0.125f;
        g_KQ[((size_t)(2 * j + 1) * 64 + eh) * 512 + d0 + t] = hi32(acc[j]) * 0.125f;
    }
}

// ---- K5: score partials (D split x2) ----
__global__ __launch_bounds__(128) void k_scores2(const float* __restrict__ retr) {
    int b = blockIdx.y, l0 = blockIdx.x * 128, ds = blockIdx.z, t = threadIdx.x;
    float* outbuf = ds ? g_sc1 : g_sc0;
    int dbase = ds * 256;
    __shared__ float rs[128][33];
    __shared__ __align__(16) float ksm[32][66];
    int lb = (t >> 3) * 8, ehb = (t & 7) * 8;
    ull acc[8][4] = {};
    for (int d0 = 0; d0 < 256; d0 += 32) {
        for (int idx = t; idx < 4096; idx += 128) {
            int l = idx >> 5, dd = idx & 31;
            rs[l][dd] = retr[((size_t)b * 2048 + l0 + l) * 512 + dbase + d0 + dd];
        }
        for (int idx = t; idx < 2048; idx += 128) {
            int eh = idx >> 5, dd = idx & 31;
            ksm[dd][eh] = g_KQ[(b * 64 + eh) * 512 + dbase + d0 + dd];
        }
        __syncthreads();
        #pragma unroll 2
        for (int dd = 0; dd < 32; dd++) {
            ull kp[4];
            #pragma unroll
            for (int j = 0; j < 4; j++) kp[j] = *(const ull*)&ksm[dd][ehb + 2 * j];
            #pragma unroll
            for (int i = 0; i < 8; i++) {
                ull rp = pack2(rs[lb + i][dd]);
                #pragma unroll
                for (int j = 0; j < 4; j++) ffma2(acc[i][j], rp, kp[j]);
            }
        }
        __syncthreads();
    }
    #pragma unroll
    for (int i = 0; i < 8; i++) {
        int l = l0 + lb + i;
        #pragma unroll
        for (int j = 0; j < 4; j++) {
            outbuf[(b * 64 + ehb + 2 * j) * 2048 + l] = lo32(acc[i][j]);
            outbuf[(b * 64 + ehb + 2 * j + 1) * 2048 + l] = hi32(acc[i][j]);
        }
    }
}

// ---- K6: sum partials + softmax ----
__global__ void k_softmax() {
    int id = blockIdx.x, t = threadIdx.x;
    const float* row0 = g_sc0 + (size_t)id * 2048;
    const float* row1 = g_sc1 + (size_t)id * 2048;
    float* row = g_scores + (size_t)id * 2048;
    __shared__ float red[256];
    float v[8];
    float m = -1e30f;
    for (int i = 0; i < 8; i++) {
        v[i] = row0[t + 256 * i] + row1[t + 256 * i];
        m = fmaxf(m, v[i]);
    }
    red[t] = m;
    __syncthreads();
    for (int s = 128; s > 0; s >>= 1) {
        if (t < s) red[t] = fmaxf(red[t], red[t + s]);
        __syncthreads();
    }
    m = red[0];
    __syncthreads();
    float z = 0.f;
    for (int i = 0; i < 8; i++) {
        v[i] = __expf(v[i] - m);
        z += v[i];
    }
    red[t] = z;
    __syncthreads();
    for (int s = 128; s > 0; s >>= 1) {
        if (t < s) red[t] += red[t + s];
        __syncthreads();
    }
    float rz = 1.f / red[0];
    for (int i = 0; i < 8; i++) row[t + 256 * i] = v[i] * rz;
}

// ---- entropy ----
__global__ void k_entropy() {
    int e = blockIdx.x, b = blockIdx.y, t = threadIdx.x;
    __shared__ float red[256];
    float acc = 0.f;
    for (int i = 0; i < 8; i++) {
        int l = t + i * 256;
        float p = 0.f;
        #pragma unroll
        for (int h = 0; h < 8; h++)
            p += g_scores[((size_t)b * 64 + e * 8 + h) * 2048 + l];
        p *= 0.125f;
        p = fmaxf(p, 1e-12f);
        acc -= p * __logf(p);
    }
    red[t] = acc;
    __syncthreads();
    for (int s = 128; s > 0; s >>= 1) {
        if (t < s) red[t] += red[t + s];
        __syncthreads();
    }
    if (t == 0) g_hent[b * 8 + e] = red[0];
}

// ---- K7: r partials (d-tile 128, L split x4, 256 threads, grid 256) ----
__global__ __launch_bounds__(256) void k_r4m(const float* __restrict__ retr) {
    int dt = blockIdx.x, b = blockIdx.y, ls = blockIdx.z, t = threadIdx.x;
    int d0 = dt * 128, lbase = ls * 512;
    __shared__ __align__(16) float rs[32][132];
    __shared__ float ps[64][33];
    int ehb = (t >> 4) * 4, dg = t & 15;
    ull acc[4][4] = {};
    for (int l0 = 0; l0 < 512; l0 += 32) {
        for (int idx = t; idx < 4096; idx += 256) {
            int l = idx >> 7, dd = idx & 127;
            rs[l][dd] = retr[((size_t)b * 2048 + lbase + l0 + l) * 512 + d0 + dd];
        }
        for (int idx = t; idx < 2048; idx += 256) {
            int eh = idx >> 5, ll = idx & 31;
            ps[eh][ll] = g_scores[(b * 64 + eh) * 2048 + lbase + l0 + ll];
        }
        __syncthreads();
        #pragma unroll 2
        for (int ll = 0; ll < 32; ll++) {
            ull rp[4];
            #pragma unroll
            for (int j = 0; j < 4; j++) rp[j] = *(const ull*)&rs[ll][dg * 2 + j * 32];
            #pragma unroll
            for (int i = 0; i < 4; i++) {
                ull pp = pack2(ps[ehb + i][ll]);
                #pragma unroll
                for (int j = 0; j < 4; j++) ffma2(acc[i][j], pp, rp[j]);
            }
        }
        __syncthreads();
    }
    #pragma unroll
    for (int i = 0; i < 4; i++)
        #pragma unroll
        for (int j = 0; j < 4; j++) {
            float2 v = make_float2(lo32(acc[i][j]), hi32(acc[i][j]));
            *(float2*)&g_rp[((size_t)ls * 524288) + ((size_t)b * 64 + ehb + i) * 512 + d0 + dg * 2 + j * 32] = v;
        }
}

// ---- K8: attn partials (K split x8; folds r-partial reduction) ----
__global__ __launch_bounds__(128) void k_attn8(const float* __restrict__ Wv) {
    int kt = blockIdx.x, e = blockIdx.y, ks = blockIdx.z, t = threadIdx.x;
    int k = kt * 128 + t, h0 = kt * 2, hl = t >> 6;
    __shared__ __align__(16) float rsm[64][2][16];
    int d0 = ks * 64;
    for (int idx = t; idx < 2048; idx += 128) {
        int dd = idx >> 5, rrem = idx & 31;
        int hl2 = rrem >> 4, bb = rrem & 15;
        size_t base = ((size_t)bb * 64 + e * 8 + h0 + hl2) * 512 + d0 + dd;
        rsm[dd][hl2][bb] = g_rp[base] + g_rp[524288 + base]
                         + g_rp[1048576 + base] + g_rp[1572864 + base];
    }
    __syncthreads();
    ull acc[8] = {};
    const float* w = Wv + (size_t)e * 262144 + (size_t)d0 * 512 + k;
    #pragma unroll 8
    for (int dd = 0; dd < 64; dd++) {
        ull wp = pack2(w[dd * 512]);
        #pragma unroll
        for (int j = 0; j < 8; j++) ffma2(acc[j], *(const ull*)&rsm[dd][hl][2 * j], wp);
    }
    #pragma unroll
    for (int j = 0; j < 8; j++) {
        g_ap[((size_t)(ks * 16 + 2 * j) * 8 + e) * 512 + k] = lo32(acc[j]);
        g_ap[((size_t)(ks * 16 + 2 * j + 1) * 8 + e) * 512 + k] = hi32(acc[j]);
    }
}

// ---- K9: wo partials (K split x4; folds bv + ap reduction) ----
__global__ __launch_bounds__(128) void k_wo4(const float* __restrict__ Wo,
                                             const float* __restrict__ bv) {
    int kt = blockIdx.x, e = blockIdx.y, ks = blockIdx.z, t = threadIdx.x;
    __shared__ __align__(16) float asm_[128][16];
    int d0 = ks * 128;
    for (int idx = t; idx < 2048; idx += 128) {
        int d = idx >> 4, b = idx & 15;
        float s = bv[e * 512 + d0 + d];
        #pragma unroll
        for (int kz = 0; kz < 8; kz++)
            s += g_ap[((size_t)(kz * 16 + b) * 8 + e) * 512 + d0 + d];
        asm_[d][b] = s;
    }
    __syncthreads();
    int k = kt * 128 + t;
    ull acc[8] = {};
    const float* w = Wo + (size_t)e * 262144 + (size_t)d0 * 512 + k;
    #pragma unroll 8
    for (int d = 0; d < 128; d++) {
        ull wp = pack2(w[d * 512]);
        #pragma unroll
        for (int j = 0; j < 8; j++) ffma2(acc[j], *(const ull*)&asm_[d][2 * j], wp);
    }
    #pragma unroll
    for (int j = 0; j < 8; j++) {
        g_op[((size_t)(ks * 16 + 2 * j) * 8 + e) * 512 + k] = lo32(acc[j]);
        g_op[((size_t)(ks * 16 + 2 * j + 1) * 8 + e) * 512 + k] = hi32(acc[j]);
    }
}

// ---- K10: reduce op + bo + residual, then LN -> x, xo (fused) ----
__global__ void k_bo_lno(const float* __restrict__ bo, const float* __restrict__ q,
                         const float* __restrict__ lng, const float* __restrict__ lnb) {
    int e = blockIdx.x, b = blockIdx.y, t = threadIdx.x;
    float xv[2];
    #pragma unroll
    for (int half = 0; half < 2; half++) {
        int col = t + half * 256;
        float s = bo[e * 512 + col] + q[b * 512 + col];
        #pragma unroll
        for (int ks = 0; ks < 4; ks++)
            s += g_op[((size_t)(ks * 16 + b) * 8 + e) * 512 + col];
        g_x[((size_t)b * 8 + e) * 512 + col] = s;
        xv[half] = s;
    }
    __shared__ float r1[256], r2[256];
    r1[t] = xv[0] + xv[1]; r2[t] = xv[0] * xv[0] + xv[1] * xv[1];
    __syncthreads();
    for (int s = 128; s > 0; s >>= 1) {
        if (t < s) { r1[t] += r1[t + s]; r2[t] += r2[t + s]; }
        __syncthreads();
    }
    float mu = r1[0] * (1.f / 512.f);
    float var = r2[0] * (1.f / 512.f) - mu * mu;
    float rstd = rsqrtf(var + 1e-5f);
    float* o = g_xo + ((size_t)b * 8 + e) * 512;
    o[t] = (xv[0] - mu) * rstd * lng[e * 512 + t] + lnb[e * 512 + t];
    o[t + 256] = (xv[1] - mu) * rstd * lng[e * 512 + t + 256] + lnb[e * 512 + t + 256];
}

// ---- K11: ffn1 partials (K split x4, unroll 4) ----
__global__ __launch_bounds__(128) void k_ffn14(const float* __restrict__ W1) {
    int ft = blockIdx.x * 256, e = blockIdx.y, ks = blockIdx.z, t = threadIdx.x;
    __shared__ __align__(16) float xsm[128][16];
    int d0 = ks * 128;
    for (int idx = t; idx < 2048; idx += 128) {
        int d = idx >> 4, b = idx & 15;
        xsm[d][b] = g_xo[((size_t)b * 8 + e) * 512 + d0 + d];
    }
    __syncthreads();
    int f0 = ft + t * 2;
    ull acc[2][8] = {};
    const float* w = W1 + (size_t)e * 1048576 + (size_t)d0 * 2048 + f0;
    #pragma unroll 4
    for (int d = 0; d < 128; d++) {
        float2 wv = *(const float2*)&w[(size_t)d * 2048];
        ull wp0 = pack2(wv.x), wp1 = pack2(wv.y);
        #pragma unroll
        for (int j = 0; j < 8; j++) {
            ull q2 = *(const ull*)&xsm[d][2 * j];
            ffma2(acc[0][j], q2, wp0);
            ffma2(acc[1][j], q2, wp1);
        }
    }
    #pragma unroll
    for (int s = 0; s < 2; s++)
        #pragma unroll
        for (int j = 0; j < 8; j++) {
            g_h1p[((size_t)(ks * 16 + 2 * j) * 8 + e) * 2048 + f0 + s] = lo32(acc[s][j]);
            g_h1p[((size_t)(ks * 16 + 2 * j + 1) * 8 + e) * 2048 + f0 + s] = hi32(acc[s][j]);
        }
}

// ---- K12: ffn2 partials (K split x16; folds b1 + gelu into staging) ----
__global__ __launch_bounds__(128) void k_ffn216(const float* __restrict__ W2,
                                                const float* __restrict__ b1) {
    int dt = blockIdx.x, e = blockIdx.y, ks = blockIdx.z, t = threadIdx.x;
    __shared__ __align__(16) float hsm[128][16];
    for (int idx = t; idx < 2048; idx += 128) {
        int k = idx >> 4, b = idx & 15;
        int col = ks * 128 + k;
        float s = b1[e * 2048 + col];
        #pragma unroll
        for (int j = 0; j < 4; j++)
            s += g_h1p[((size_t)(j * 16 + b) * 8 + e) * 2048 + col];
        hsm[k][b] = 0.5f * s * (1.f + erff(s * 0.70710678118654752f));
    }
    __syncthreads();
    int d = dt * 128 + t;
    ull acc[8] = {};
    const float* w = W2 + (size_t)e * 1048576 + (size_t)ks * 128 * 512 + d;
    #pragma unroll 8
    for (int k = 0; k < 128; k++) {
        ull wp = pack2(w[(size_t)k * 512]);
        #pragma unroll
        for (int j = 0; j < 8; j++) ffma2(acc[j], *(const ull*)&hsm[k][2 * j], wp);
    }
    #pragma unroll
    for (int j = 0; j < 8; j++) {
        g_yp[((size_t)(ks * 16 + 2 * j) * 8 + e) * 512 + d] = lo32(acc[j]);
        g_yp[((size_t)(ks * 16 + 2 * j + 1) * 8 + e) * 512 + d] = hi32(acc[j]);
    }
}

// ---- K14: combine ----
__global__ void k_final(const float* __restrict__ b2, float* __restrict__ out_f,
                        float* __restrict__ out_y, float* __restrict__ out_gt,
                        int write_full) {
    int b = blockIdx.x, t = threadIdx.x;
    __shared__ float gts[8];
    __shared__ float ssum;
    if (t < 8) gts[t] = g_gates[b * 8 + t] * __expf(-0.5f * g_hent[b * 8 + t]);
    __syncthreads();
    if (t == 0) {
        float s = 0.f;
        for (int i = 0; i < 8; i++) s += gts[i];
        ssum = 1.f / (s + 1e-9f);
    }
    __syncthreads();
    float rz = ssum;
    int d = t;
    float fused = 0.f;
    #pragma unroll
    for (int e = 0; e < 8; e++) {
        float yv = g_x[(b * 8 + e) * 512 + d] + b2[e * 512 + d];
        #pragma unroll
        for (int ks = 0; ks < 16; ks++)
            yv += g_yp[(((size_t)ks * 16 + b) * 8 + e) * 512 + d];
        fused += gts[e] * rz * yv;
        if (write_full) out_y[((size_t)b * 8 + e) * 512 + d] = yv;
    }
    out_f[b * 512 + d] = fused;
    if (write_full && t < 8) out_gt[b * 8 + t] = gts[t] * rz;
}

extern "C" void kernel_launch(void* const* d_in, const int* in_sizes, int n_in,
                              void* d_out, int out_size) {
    const float* query = (const float*)d_in[0];
    const float* retrieved = (const float*)d_in[1];
    const float* w_gate = (const float*)d_in[2];
    const float* ln_q_g = (const float*)d_in[3];
    const float* ln_q_b = (const float*)d_in[4];
    const float* Wq = (const float*)d_in[5];
    const float* bq = (const float*)d_in[6];
    const float* Wk = (const float*)d_in[7];
    const float* Wv = (const float*)d_in[9];
    const float* bv = (const float*)d_in[10];
    const float* Wo = (const float*)d_in[11];
    const float* bo = (const float*)d_in[12];
    const float* ln_o_g = (const float*)d_in[13];
    const float* ln_o_b = (const float*)d_in[14];
    const float* W1 = (const float*)d_in[15];
    const float* b1 = (const float*)d_in[16];
    const float* W2 = (const float*)d_in[17];
    const float* b2 = (const float*)d_in[18];

    float* out = (float*)d_out;
    int write_full = (out_size >= 8192 + 65536 + 128) ? 1 : 0;
    float* out_f = out;
    float* out_y = write_full ? out + 8192 : out;
    float* out_gt = write_full ? out + 8192 + 65536 : out;

    k_gates<<<16, 256>>>(query, w_gate);
    k_lnq<<<16, 256>>>(query);
    k_qh4<<<dim3(4, 8, 4), 128>>>(Wq, ln_q_g, ln_q_b);
    k_KQt<<<dim3(4, 8, 8), 128>>>(Wk, bq);
    k_scores2<<<dim3(16, 16, 2), 128>>>(retrieved);
    k_softmax<<<1024, 256>>>();
    k_entropy<<<dim3(8, 16), 256>>>();
    k_r4m<<<dim3(4, 16, 4), 256>>>(retrieved);
    k_attn8<<<dim3(4, 8, 8), 128>>>(Wv);
    k_wo4<<<dim3(4, 8, 4), 128>>>(Wo, bv);
    k_bo_lno<<<dim3(8, 16), 256>>>(bo, query, ln_o_g, ln_o_b);
    k_ffn14<<<dim3(8, 8, 4), 128>>>(W1);
    k_ffn216<<<dim3(4, 8, 16), 128>>>(W2, b1);
    k_final<<<16, 512>>>(b2, out_f, out_y, out_gt, write_full);
}